// round 4
// baseline (speedup 1.0000x reference)
#include <cuda_runtime.h>
#include <math.h>

#define NQ       10
#define DIM      1024          // 2^NQ
#define NL       3
#define NG       (NL * NQ)     // 30 fused gates
#define THREADS  512
#define NWARPS   (THREADS / 32)
#define PI_F     3.14159265358979f

__device__ __forceinline__ float2 cmul(float2 a, float2 b) {
    return make_float2(a.x * b.x - a.y * b.y, a.x * b.y + a.y * b.x);
}

// Composition of the 10-CNOT ring (control i, target (i+1)%10), applied as
// state_new[k] = state_old[P(k)] with P = p0 ∘ p1 ∘ ... ∘ p9 (p9 innermost).
__device__ __forceinline__ int cnot_chain(int k) {
#pragma unroll
    for (int i = NQ - 1; i >= 0; --i) {
        const int tq = (i + 1) % NQ;
        const int cb = (k >> (NQ - 1 - i)) & 1;
        k ^= cb << (NQ - 1 - tq);
    }
    return k;
}

__global__ __launch_bounds__(THREADS)
void vq_kernel(const float* __restrict__ x,
               const float* __restrict__ w,
               float* __restrict__ out)
{
    __shared__ float2 st[DIM];          // statevector (8 KB)
    __shared__ float2 U[NG * 4];        // fused RZ*RY*RX 2x2 per (layer,qubit)
    __shared__ float  encc[NQ], encs[NQ];
    __shared__ float  wpart[NWARPS][NQ];

    const int t = threadIdx.x;
    const int b = blockIdx.x;

    // ---- setup (warp 0: fused gate matrices; warp 2: encoding angles) ----
    if (t < NG) {
        const float ax = w[t * 3 + 0];  // RX angle
        const float ay = w[t * 3 + 1];  // RY angle
        const float az = w[t * 3 + 2];  // RZ angle
        float ca, sa, cb, sb, cg, sg;
        sincosf(0.5f * ax, &sa, &ca);
        sincosf(0.5f * ay, &sb, &cb);
        sincosf(0.5f * az, &sg, &cg);
        // M = RY @ RX
        const float2 M00 = make_float2( cb * ca,  sb * sa);
        const float2 M01 = make_float2(-sb * ca, -cb * sa);
        const float2 M10 = make_float2( sb * ca, -cb * sa);
        const float2 M11 = make_float2( cb * ca, -sb * sa);
        // U = RZ @ M : row0 *= e^{-i g/2}, row1 *= e^{+i g/2}
        const float2 e0 = make_float2(cg, -sg);
        const float2 e1 = make_float2(cg,  sg);
        U[t * 4 + 0] = cmul(e0, M00);
        U[t * 4 + 1] = cmul(e0, M01);
        U[t * 4 + 2] = cmul(e1, M10);
        U[t * 4 + 3] = cmul(e1, M11);
    }
    if (t >= 64 && t < 64 + NQ) {
        const int q = t - 64;
        const float a = tanhf(x[b * NQ + q]) * PI_F;
        float c, s;
        sincosf(0.5f * a, &s, &c);
        encc[q] = c;
        encs[q] = s;
    }
    __syncthreads();

    // ---- initial product state (RY encoding on |0...0> is real) ----
    {
        const int k0 = t, k1 = t + THREADS;
        float a0 = 1.0f, a1 = 1.0f;
#pragma unroll
        for (int q = 0; q < NQ; ++q) {
            const int p = NQ - 1 - q;
            a0 *= ((k0 >> p) & 1) ? encs[q] : encc[q];
            a1 *= ((k1 >> p) & 1) ? encs[q] : encc[q];
        }
        st[k0] = make_float2(a0, 0.0f);
        st[k1] = make_float2(a1, 0.0f);
    }

    // ---- layers ----
    for (int l = 0; l < NL; ++l) {
        // composed CNOT-ring permutation: one gather pass
        __syncthreads();
        const float2 tA = st[cnot_chain(t)];
        const float2 tB = st[cnot_chain(t + THREADS)];
        __syncthreads();
        st[t]           = tA;
        st[t + THREADS] = tB;

        // fused RZ*RY*RX per qubit
#pragma unroll
        for (int q = 0; q < NQ; ++q) {
            __syncthreads();
            const int m   = 1 << (NQ - 1 - q);
            const int low = t & (m - 1);
            const int i0  = ((t ^ low) << 1) | low;
            const int i1  = i0 | m;
            const float2 a0 = st[i0];
            const float2 a1 = st[i1];
            const int g = (l * NQ + q) * 4;
            const float2 u00 = U[g + 0], u01 = U[g + 1];
            const float2 u10 = U[g + 2], u11 = U[g + 3];
            const float2 r0 = cmul(u00, a0), r0b = cmul(u01, a1);
            const float2 r1 = cmul(u10, a0), r1b = cmul(u11, a1);
            st[i0] = make_float2(r0.x + r0b.x, r0.y + r0b.y);
            st[i1] = make_float2(r1.x + r1b.x, r1.y + r1b.y);
        }
    }

    __syncthreads();

    // ---- Z expectations: out[b][w] = sum_k p_k * (1 - 2*bit_{9-w}(k)) ----
    float acc[NQ];
    {
        const float2 A = st[t];
        const float2 B = st[t + THREADS];
        const float p0 = A.x * A.x + A.y * A.y;
        const float p1 = B.x * B.x + B.y * B.y;
        const int k1 = t + THREADS;
#pragma unroll
        for (int wq = 0; wq < NQ; ++wq) {
            const int p = NQ - 1 - wq;
            const float s0 = ((t  >> p) & 1) ? -p0 : p0;
            const float s1 = ((k1 >> p) & 1) ? -p1 : p1;
            acc[wq] = s0 + s1;
        }
    }
#pragma unroll
    for (int wq = 0; wq < NQ; ++wq) {
#pragma unroll
        for (int off = 16; off > 0; off >>= 1)
            acc[wq] += __shfl_xor_sync(0xffffffffu, acc[wq], off);
    }
    const int warp = t >> 5, lane = t & 31;
    if (lane == 0) {
#pragma unroll
        for (int wq = 0; wq < NQ; ++wq) wpart[warp][wq] = acc[wq];
    }
    __syncthreads();
    if (t < NQ) {
        float s = 0.0f;
#pragma unroll
        for (int i = 0; i < NWARPS; ++i) s += wpart[i][t];
        out[b * NQ + t] = s;
    }
}

extern "C" void kernel_launch(void* const* d_in, const int* in_sizes, int n_in,
                              void* d_out, int out_size) {
    const float* x = (const float*)d_in[0];
    const float* w = (const float*)d_in[1];
    // Defensive: identify the weights tensor (3*10*3 = 90 elems) by size.
    if (n_in >= 2 && in_sizes[0] == NG * 3 && in_sizes[1] != NG * 3) {
        x = (const float*)d_in[1];
        w = (const float*)d_in[0];
    }
    const int batch = out_size / NQ;   // 16384
    vq_kernel<<<batch, THREADS>>>(x, w, (float*)d_out);
}

// round 6
// speedup vs baseline: 2.8171x; 2.8171x over previous
#include <cuda_runtime.h>
#include <math.h>

#define NQ       10
#define DIM      1024
#define NL       3
#define NG       (NL * NQ)
#define WPB      4                 // warps (batch elements) per block
#define THREADS  (WPB * 32)
#define PI_F     3.14159265358979f

// ---------------- packed f32x2 helpers (sm_103a) ----------------
union F2U { float2 f; unsigned long long u; };

__device__ __forceinline__ float2 f2mul(float2 a, float2 b) {
    F2U A, B, D; A.f = a; B.f = b;
    asm("mul.rn.f32x2 %0, %1, %2;" : "=l"(D.u) : "l"(A.u), "l"(B.u));
    return D.f;
}
__device__ __forceinline__ float2 f2fma(float2 a, float2 b, float2 c) {
    F2U A, B, C, D; A.f = a; B.f = b; C.f = c;
    asm("fma.rn.f32x2 %0, %1, %2, %3;" : "=l"(D.u) : "l"(A.u), "l"(B.u), "l"(C.u));
    return D.f;
}

__device__ __forceinline__ float2 cmul(float2 a, float2 b) {
    return make_float2(a.x * b.x - a.y * b.y, a.x * b.y + a.y * b.x);
}

// Composed CNOT ring (control i -> target (i+1)%10), closed form.
// state_new[k] = state_old[P(k)];  P(k) = k ^ (k>>1) ^ (b0 ? 0x300 : 0)
__device__ __forceinline__ int cnot_perm(int k) {
    return k ^ (k >> 1) ^ ((-(k & 1)) & 0x300);
}

// smem swizzle: stride-33 rows of 32 float2 -> conflict-minimal
__device__ __forceinline__ int phys(int k) { return k + (k >> 5); }

// Gate coefficients, packed per u-element as (x, x, -y, y).
// Order per gate: u00, u01, u10, u11.
__device__ float4 g_gco[NG][4];

// ---------------- prep kernel: fuse RZ*RY*RX per (layer,qubit) ----------------
__global__ void vq_prep(const float* __restrict__ w) {
    const int t = threadIdx.x;
    if (t >= NG) return;
    const float ax = w[t * 3 + 0];
    const float ay = w[t * 3 + 1];
    const float az = w[t * 3 + 2];
    float ca, sa, cb, sb, cg, sg;
    sincosf(0.5f * ax, &sa, &ca);
    sincosf(0.5f * ay, &sb, &cb);
    sincosf(0.5f * az, &sg, &cg);
    // M = RY @ RX
    const float2 M00 = make_float2( cb * ca,  sb * sa);
    const float2 M01 = make_float2(-sb * ca, -cb * sa);
    const float2 M10 = make_float2( sb * ca, -cb * sa);
    const float2 M11 = make_float2( cb * ca, -sb * sa);
    // U = RZ @ M
    const float2 e0 = make_float2(cg, -sg);
    const float2 e1 = make_float2(cg,  sg);
    const float2 u00 = cmul(e0, M00);
    const float2 u01 = cmul(e0, M01);
    const float2 u10 = cmul(e1, M10);
    const float2 u11 = cmul(e1, M11);
    g_gco[t][0] = make_float4(u00.x, u00.x, -u00.y, u00.y);
    g_gco[t][1] = make_float4(u01.x, u01.x, -u01.y, u01.y);
    g_gco[t][2] = make_float4(u10.x, u10.x, -u10.y, u10.y);
    g_gco[t][3] = make_float4(u11.x, u11.x, -u11.y, u11.y);
}

// Apply fused gate with register-bit mask RM to the 32 register-resident amps.
template<int RM>
__device__ __forceinline__ void apply_gate(float2 a[32], int g) {
    const float4 q0 = __ldg(&g_gco[g][0]);
    const float4 q1 = __ldg(&g_gco[g][1]);
    const float4 q2 = __ldg(&g_gco[g][2]);
    const float4 q3 = __ldg(&g_gco[g][3]);
    const float2 u00x = make_float2(q0.x, q0.y), u00m = make_float2(q0.z, q0.w);
    const float2 u01x = make_float2(q1.x, q1.y), u01m = make_float2(q1.z, q1.w);
    const float2 u10x = make_float2(q2.x, q2.y), u10m = make_float2(q2.z, q2.w);
    const float2 u11x = make_float2(q3.x, q3.y), u11m = make_float2(q3.z, q3.w);
#pragma unroll
    for (int r = 0; r < 32; ++r) {
        if (r & RM) continue;
        const float2 a0 = a[r];
        const float2 a1 = a[r | RM];
        const float2 s0 = make_float2(a0.y, a0.x);
        const float2 s1 = make_float2(a1.y, a1.x);
        float2 r0 = f2mul(u00x, a0);
        r0 = f2fma(u00m, s0, r0);
        r0 = f2fma(u01x, a1, r0);
        r0 = f2fma(u01m, s1, r0);
        float2 r1 = f2mul(u10x, a0);
        r1 = f2fma(u10m, s0, r1);
        r1 = f2fma(u11x, a1, r1);
        r1 = f2fma(u11m, s1, r1);
        a[r]      = r0;
        a[r | RM] = r1;
    }
}

// ---------------- main kernel: 1 warp = 1 batch element ----------------
__global__ __launch_bounds__(THREADS, 4)
void vq_main(const float* __restrict__ x, float* __restrict__ out) {
    __shared__ float2 sh[WPB][DIM + 32];   // 33.8 KB, one swizzled region per warp

    const int t  = threadIdx.x;
    const int wi = t >> 5;
    const int L  = t & 31;
    const int b  = blockIdx.x * WPB + wi;
    float2* const st = sh[wi];

    // ---- per-batch encoding angles: lanes 0..9 compute, broadcast ----
    float c = 1.0f, s = 0.0f;
    if (L < NQ) {
        const float a = tanhf(x[b * NQ + L]) * PI_F;
        sincosf(0.5f * a, &s, &c);
    }
    float cq[NQ], sq[NQ];
#pragma unroll
    for (int q = 0; q < NQ; ++q) {
        cq[q] = __shfl_sync(0xffffffffu, c, q);
        sq[q] = __shfl_sync(0xffffffffu, s, q);
    }

    // ---- initial product state, Layout A: k = (L<<5) | r ----
    // qubit q bit index = 9-q;  lane bits = 9..5 (qubits 0..4), reg bits = 4..0 (qubits 5..9)
    float lf = 1.0f;
#pragma unroll
    for (int q = 0; q < 5; ++q)
        lf *= ((L >> (4 - q)) & 1) ? sq[q] : cq[q];

    float2 a[32];
#pragma unroll
    for (int r = 0; r < 32; ++r) {
        float rf = lf;
#pragma unroll
        for (int q = 5; q < NQ; ++q)
            rf *= ((r >> (9 - q)) & 1) ? sq[q] : cq[q];
        a[r] = make_float2(rf, 0.0f);
    }

    // ---- layers ----
#pragma unroll
    for (int l = 0; l < NL; ++l) {
        // write canonical state from current layout (A for l==0, else B),
        // then gather through the composed CNOT permutation into Layout A
        __syncwarp();
        if (l == 0) {
#pragma unroll
            for (int r = 0; r < 32; ++r) st[phys((L << 5) | r)] = a[r];
        } else {
#pragma unroll
            for (int r = 0; r < 32; ++r) st[phys((r << 5) | L)] = a[r];
        }
        __syncwarp();
#pragma unroll
        for (int r = 0; r < 32; ++r) a[r] = st[phys(cnot_perm((L << 5) | r))];

        // gates on qubits 5..9 (register bits in Layout A); commuting 1q gates
        // reordered: q5..q9 first, then q0..q4 after transpose
        apply_gate<16>(a, l * NQ + 5);
        apply_gate<8 >(a, l * NQ + 6);
        apply_gate<4 >(a, l * NQ + 7);
        apply_gate<2 >(a, l * NQ + 8);
        apply_gate<1 >(a, l * NQ + 9);

        // transpose to Layout B: k = (r<<5) | L
        __syncwarp();
#pragma unroll
        for (int r = 0; r < 32; ++r) st[phys((L << 5) | r)] = a[r];
        __syncwarp();
#pragma unroll
        for (int r = 0; r < 32; ++r) a[r] = st[phys((r << 5) | L)];

        // gates on qubits 0..4 (register bits in Layout B): q -> mask 1<<(4-q)
        apply_gate<16>(a, l * NQ + 0);
        apply_gate<8 >(a, l * NQ + 1);
        apply_gate<4 >(a, l * NQ + 2);
        apply_gate<2 >(a, l * NQ + 3);
        apply_gate<1 >(a, l * NQ + 4);
    }

    // ---- Z expectations (state in Layout B: k = (r<<5) | L) ----
    // w in 0..4: sign bit = bit (4-w) of r (compile-time per register)
    // w in 5..9: sign bit = bit (9-w) of L (uniform over r)
    float acc[5] = {0.f, 0.f, 0.f, 0.f, 0.f};
    float T = 0.0f;
#pragma unroll
    for (int r = 0; r < 32; ++r) {
        const float p = a[r].x * a[r].x + a[r].y * a[r].y;
        T += p;
#pragma unroll
        for (int w = 0; w < 5; ++w)
            acc[w] += ((r >> (4 - w)) & 1) ? -p : p;
    }

    float red[NQ];
#pragma unroll
    for (int w = 0; w < 5; ++w) red[w] = acc[w];
#pragma unroll
    for (int j = 0; j < 5; ++j)
        red[5 + j] = ((L >> (4 - j)) & 1) ? -T : T;

#pragma unroll
    for (int w = 0; w < NQ; ++w) {
#pragma unroll
        for (int off = 16; off > 0; off >>= 1)
            red[w] += __shfl_xor_sync(0xffffffffu, red[w], off);
    }

    if (L == 0) {
#pragma unroll
        for (int w = 0; w < NQ; ++w)
            out[b * NQ + w] = red[w];
    }
}

extern "C" void kernel_launch(void* const* d_in, const int* in_sizes, int n_in,
                              void* d_out, int out_size) {
    const float* x = (const float*)d_in[0];
    const float* w = (const float*)d_in[1];
    if (n_in >= 2 && in_sizes[0] == NG * 3 && in_sizes[1] != NG * 3) {
        x = (const float*)d_in[1];
        w = (const float*)d_in[0];
    }
    const int batch = out_size / NQ;            // 16384
    vq_prep<<<1, 32>>>(w);
    vq_main<<<batch / WPB, THREADS>>>(x, (float*)d_out);
}